// round 14
// baseline (speedup 1.0000x reference)
#include <cuda_runtime.h>

// ConvCNP via 1-D Fast Gauss Transform (Hermite expansion, P=20), two kernels
// with PDL overlap.
//   Kernel 1 (64 blocks): per (batch, box-slot) computes FINAL scaled
//     coefficients g_coef[b][box][40] = {ch0 k=0..19, ch1 k=0..19} * 1/k!
//     plus an 8-float geometry record g_geom. Context is prefetched before
//     the sigma chain; reduction = 31-shuffle butterfly (32 vals) + 40-shuffle
//     tree (8 vals).
//   Kernel 2: UNCHANGED from the measured 10.7us best — per-target Horner
//     eval + 64-wide linear epilogue, coherent staged reads behind
//     cudaGridDependencySynchronize.
//
// h_{k+1} = 2x h_k - 2k h_{k-1}; boxes of width sqrt(delta_min) => |z|<=0.5;
// truncation at P=20 ~1e-12 per pair. Brute-force fallback if nbox > MAXBOX.

#define BATCH  4
#define NCTX   2048
#define MTGT   8192
#define NOUT   64
#define P      20
#define NW     (2 * P)            // 40 words per (b,box)
#define MAXBOX 64
#define BSLOTS 16                 // box slots per batch in kernel-1 grid
#define BLK1   256
#define GRID1  (BATCH * BSLOTS)   // 64 blocks
#define PPT    (NCTX / BLK1)      // 8 points per thread in kernel 1
#define TTILE  64
#define BLK2   256
#define GRID2  ((BATCH * MTGT) / TTILE)   // 512
#define XMIN   (-8.0f)
#define XRANGE 16.0f
#define SQRT2  1.41421356237f
#define LOG2E  1.44269504089f

__device__ float g_coef[BATCH * MAXBOX * NW];
__device__ float g_geom[8];   // {wbox, inv_wbox, inv_sd0, inv_sd1, nboxf, k0c, k1c, fgt_ok}

__constant__ float c_invfact[P] = {
    1.0f, 1.0f, 0.5f, 1.6666667e-1f, 4.1666667e-2f,
    8.3333333e-3f, 1.3888889e-3f, 1.9841270e-4f, 2.4801587e-5f, 2.7557319e-6f,
    2.7557319e-7f, 2.5052108e-8f, 2.0876757e-9f, 1.6059044e-10f, 1.1470746e-11f,
    7.6471637e-13f, 4.7794773e-14f, 2.8114573e-15f, 1.5619206e-16f, 8.2206352e-18f
};

__device__ __forceinline__ float ex2f(float x) {
    float y; asm("ex2.approx.f32 %0, %1;" : "=f"(y) : "f"(x)); return y;
}

// ---------------- Kernel 1: finalized Hermite coefficients ----------------
__global__ __launch_bounds__(BLK1) void coef_kernel(
    const float* __restrict__ context_in,    // [B, N]
    const float* __restrict__ context_out,   // [B, N]
    const float* __restrict__ sigma)         // [2]
{
    // Let the dependent eval kernel launch immediately (PDL).
    cudaTriggerProgrammaticLaunchCompletion();

    __shared__ float s_red[BLK1 / 32][NW + 1];   // +1 pad for the column fold

    const int b    = blockIdx.x >> 4;        // / BSLOTS
    const int slot = blockIdx.x & (BSLOTS - 1);
    const int tid  = threadIdx.x;
    const int lane = tid & 31, wrp = tid >> 5;

    // Prefetch context BEFORE the sigma-dependent chain. Only 64 blocks exist,
    // and 48+ of them use this data — the DRAM latency hides under sigma+expf.
    const float* __restrict__ uin = context_in  + b * NCTX;
    const float* __restrict__ win = context_out + b * NCTX;
    float u8[PPT], w8[PPT];
    #pragma unroll
    for (int i = 0; i < PPT; i++) {
        u8[i] = uin[tid + i * BLK1];
        w8[i] = win[tid + i * BLK1];
    }

    const float s0 = __expf(sigma[0]), s1 = __expf(sigma[1]);
    const float sd0 = s0 * SQRT2, sd1 = s1 * SQRT2;      // sqrt(delta_c)
    const float wbox = fminf(sd0, sd1);
    const int   nbox = (int)ceilf(XRANGE / wbox);
    const bool  fgt_ok = (nbox <= MAXBOX);

    if (blockIdx.x == 0 && tid == 0) {
        g_geom[0] = wbox;
        g_geom[1] = 1.0f / wbox;
        g_geom[2] = 1.0f / sd0;
        g_geom[3] = 1.0f / sd1;
        g_geom[4] = (float)nbox;
        g_geom[5] = -0.5f * LOG2E / (s0 * s0);   // brute-force k0
        g_geom[6] = -0.5f * LOG2E / (s1 * s1);   // brute-force k1
        g_geom[7] = fgt_ok ? 1.0f : 0.0f;
    }
    if (!fgt_ok || slot >= nbox) return;

    const float isd0 = 1.0f / sd0, isd1 = 1.0f / sd1;
    const bool eqscale = (sd0 == sd1);

    for (int box = slot; box < nbox; box += BSLOTS) {
        const float cbox = XMIN + (box + 0.5f) * wbox;

        // r[0..19] = ch0 (density), r[20..39] = ch1 (numerator).
        float r[NW];
        #pragma unroll
        for (int k = 0; k < NW; k++) r[k] = 0.0f;

        if (eqscale) {
            // Equal scales: one recurrence feeds both channels.
            #pragma unroll
            for (int i = 0; i < PPT; i++) {
                const float u = u8[i], w = w8[i];
                const float t  = (u - cbox) * isd0;
                const float h0 = ex2f(-t * t * LOG2E);
                const float t2 = t + t;
                float hm = h0, hc = t2 * h0;
                r[0] += h0;  r[P]     = fmaf(w, h0, r[P]);
                r[1] += hc;  r[P + 1] = fmaf(w, hc, r[P + 1]);
                #pragma unroll
                for (int k = 1; k < P - 1; k++) {
                    const float hn = fmaf(t2, hc, -(2.0f * k) * hm);
                    r[k + 1] += hn;  r[P + k + 1] = fmaf(w, hn, r[P + k + 1]);
                    hm = hc; hc = hn;
                }
            }
        } else {
            #pragma unroll
            for (int i = 0; i < PPT; i++) {
                const float u = u8[i], w = w8[i];
                {
                    const float t  = (u - cbox) * isd0;
                    const float h0 = ex2f(-t * t * LOG2E);
                    const float t2 = t + t;
                    float hm = h0, hc = t2 * h0;
                    r[0] += h0; r[1] += hc;
                    #pragma unroll
                    for (int k = 1; k < P - 1; k++) {
                        const float hn = fmaf(t2, hc, -(2.0f * k) * hm);
                        r[k + 1] += hn; hm = hc; hc = hn;
                    }
                }
                {
                    const float t  = (u - cbox) * isd1;
                    const float h0 = ex2f(-t * t * LOG2E);
                    const float t2 = t + t;
                    float hm = h0, hc = t2 * h0;
                    r[P] = fmaf(w, h0, r[P]); r[P + 1] = fmaf(w, hc, r[P + 1]);
                    #pragma unroll
                    for (int k = 1; k < P - 1; k++) {
                        const float hn = fmaf(t2, hc, -(2.0f * k) * hm);
                        r[P + k + 1] = fmaf(w, hn, r[P + k + 1]); hm = hc; hc = hn;
                    }
                }
            }
        }

        // Warp reduction, 71 shuffles total:
        //  (a) split-butterfly on values 0..31 (31 shuffles): lane l ends
        //      holding the warp-sum of value l.
        #pragma unroll
        for (int s = 16; s >= 1; s >>= 1) {
            const bool up = (lane & s) != 0;
            #pragma unroll
            for (int i = 0; i < s; i++) {
                const float send  = up ? r[i] : r[i + s];
                const float other = __shfl_xor_sync(0xffffffffu, send, s);
                const float keep  = up ? r[i + s] : r[i];
                r[i] = keep + other;
            }
        }
        s_red[wrp][lane] = r[0];
        //  (b) plain tree on values 32..39 (8 x 5 shuffles), lane 0 writes.
        #pragma unroll
        for (int j = 0; j < NW - 32; j++) {
            float x = r[32 + j];
            #pragma unroll
            for (int off = 16; off > 0; off >>= 1)
                x += __shfl_down_sync(0xffffffffu, x, off);
            if (lane == 0) s_red[wrp][32 + j] = x;
        }
        __syncthreads();

        if (tid < NW) {
            float v = 0.0f;
            #pragma unroll
            for (int ww = 0; ww < BLK1 / 32; ww++) v += s_red[ww][tid];
            const int k = (tid < P) ? tid : (tid - P);
            g_coef[(b * MAXBOX + box) * NW + tid] = v * c_invfact[k];
        }
        if (box + BSLOTS < nbox) __syncthreads();   // s_red reuse guard
    }
}

// ---------------- Kernel 2: per-target eval + epilogue (UNCHANGED) ----------------
__global__ __launch_bounds__(BLK2) void eval_kernel(
    const float* __restrict__ context_in,
    const float* __restrict__ context_out,
    const float* __restrict__ target_in,     // [B, M]
    const float* __restrict__ W,             // [64, 2]
    const float* __restrict__ bias,          // [64]
    float* __restrict__ out)                 // [B, M, 64]
{
    __shared__ float4 s_coef4[MAXBOX * NW / 4];   // [box][40 floats]
    __shared__ float2 s_res[TTILE];

    const int tid = threadIdx.x;
    const int b   = blockIdx.x / (MTGT / TTILE);
    const int m0  = (blockIdx.x % (MTGT / TTILE)) * TTILE;
    const int tl  = tid & (TTILE - 1);

    // ---- Prologue: independent of kernel 1 (overlaps it via PDL) ----
    const float t = target_in[b * MTGT + m0 + tl];
    const int j0 = (tid & 15) * 4;
    float W0[4], W1[4], bb[4];
    #pragma unroll
    for (int q = 0; q < 4; q++) {
        W0[q] = W[(j0 + q) * 2 + 0];
        W1[q] = W[(j0 + q) * 2 + 1];
        bb[q] = bias[j0 + q];
    }

    cudaGridDependencySynchronize();   // kernel 1 results now visible

    const float4 ge0 = *(const float4*)&g_geom[0];  // wbox, inv_wbox, isd0, isd1
    const float4 ge1 = *(const float4*)&g_geom[4];  // nboxf, k0c, k1c, fgt_ok
    const int nbox = (int)ge1.x;

    float den = 0.0f, num = 0.0f;
    if (ge1.w != 0.0f) {
        // Stage this batch's coefficient table (nbox*40 floats, coalesced).
        const int nv4 = nbox * (NW / 4);
        const float4* __restrict__ src =
            (const float4*)g_coef + b * (MAXBOX * NW / 4);
        for (int i = tid; i < nv4; i += BLK2) s_coef4[i] = src[i];
        __syncthreads();

        if (tid < TTILE) {
            int bi = (int)floorf((t - XMIN) * ge0.y);
            bi = max(0, min(nbox - 1, bi));
            const float cb = XMIN + (bi + 0.5f) * ge0.x;
            const float z0 = (t - cb) * ge0.z;
            const float z1 = (t - cb) * ge0.w;

            float c[NW];
            const float4* __restrict__ cf = s_coef4 + bi * (NW / 4);
            #pragma unroll
            for (int i = 0; i < NW / 4; i++) {
                const float4 v = cf[i];
                c[i * 4 + 0] = v.x; c[i * 4 + 1] = v.y;
                c[i * 4 + 2] = v.z; c[i * 4 + 3] = v.w;
            }
            den = c[P - 1];
            num = c[NW - 1];
            #pragma unroll
            for (int k = P - 2; k >= 0; k--) {
                den = fmaf(den, z0, c[k]);
                num = fmaf(num, z1, c[P + k]);
            }
            s_res[tl] = make_float2(den, num / (den + 1e-8f));
        }
    } else {
        // Brute-force fallback (exotic sigma; uniform branch).
        if (tid < TTILE) {
            const float* __restrict__ uin = context_in  + b * NCTX;
            const float* __restrict__ win = context_out + b * NCTX;
            for (int n = 0; n < NCTX; n++) {
                const float u = __ldg(&uin[n]), w = __ldg(&win[n]);
                const float d = u - t, s = d * d;
                den += ex2f(s * ge1.y);
                num = fmaf(w, ex2f(s * ge1.z), num);
            }
            s_res[tl] = make_float2(den, num / (den + 1e-8f));
        }
    }
    __syncthreads();

    // Epilogue: 64 targets x 64 channels = 1024 float4 stores, coalesced.
    float4* __restrict__ outp = (float4*)(out + ((long)b * MTGT + m0) * NOUT);
    #pragma unroll
    for (int k = 0; k < 4; k++) {
        const int idx4 = tid + k * BLK2;    // 0..1023
        const float2 r = s_res[idx4 >> 4];
        float4 v;
        v.x = fmaf(r.x, W0[0], fmaf(r.y, W1[0], bb[0]));
        v.y = fmaf(r.x, W0[1], fmaf(r.y, W1[1], bb[1]));
        v.z = fmaf(r.x, W0[2], fmaf(r.y, W1[2], bb[2]));
        v.w = fmaf(r.x, W0[3], fmaf(r.y, W1[3], bb[3]));
        outp[idx4] = v;
    }
}

extern "C" void kernel_launch(void* const* d_in, const int* in_sizes, int n_in,
                              void* d_out, int out_size) {
    const float* context_in  = (const float*)d_in[0];
    const float* context_out = (const float*)d_in[1];
    const float* target_in   = (const float*)d_in[2];
    const float* sigma       = (const float*)d_in[3];
    const float* W           = (const float*)d_in[4];
    const float* bias        = (const float*)d_in[5];
    float* out = (float*)d_out;

    coef_kernel<<<GRID1, BLK1>>>(context_in, context_out, sigma);

    // Eval launches under PDL: its prologue overlaps kernel 1; the
    // cudaGridDependencySynchronize() inside orders the g_coef reads.
    cudaLaunchConfig_t cfg = {};
    cfg.gridDim  = dim3(GRID2, 1, 1);
    cfg.blockDim = dim3(BLK2, 1, 1);
    cfg.dynamicSmemBytes = 0;
    cfg.stream = 0;
    cudaLaunchAttribute attr[1];
    attr[0].id = cudaLaunchAttributeProgrammaticStreamSerialization;
    attr[0].val.programmaticStreamSerializationAllowed = 1;
    cfg.attrs = attr;
    cfg.numAttrs = 1;
    cudaLaunchKernelEx(&cfg, eval_kernel, context_in, context_out,
                       target_in, W, bias, out);
}